// round 15
// baseline (speedup 1.0000x reference)
#include <cuda_runtime.h>
#include <cuda_fp16.h>
#include <math.h>
#include <stdint.h>

#define BSZ 131072
#define TTR 10
#define KF 320          // padded feature dim (300 -> 320)
#define HID 1024
#define NUM_ELEM 118

// ---- scratch (device globals; no runtime allocation) ----
__device__ __half g_feat[(size_t)BSZ * KF];
__device__ __half g_h1[(size_t)BSZ * HID];
__device__ __half g_w1t[(size_t)HID * KF];    // W1^T [n][k], zero-padded
__device__ __half g_w2t[(size_t)HID * HID];   // W2^T [n][k]

// ---- helpers ----
__device__ __forceinline__ void mma16(float* c, const uint32_t* a,
                                      uint32_t b0, uint32_t b1) {
    asm volatile(
        "mma.sync.aligned.m16n8k16.row.col.f32.f16.f16.f32 "
        "{%0,%1,%2,%3}, {%4,%5,%6,%7}, {%8,%9}, {%0,%1,%2,%3};"
        : "+f"(c[0]), "+f"(c[1]), "+f"(c[2]), "+f"(c[3])
        : "r"(a[0]), "r"(a[1]), "r"(a[2]), "r"(a[3]), "r"(b0), "r"(b1));
}
__device__ __forceinline__ void ldsm4(uint32_t* r, uint32_t addr) {
    asm volatile("ldmatrix.sync.aligned.m8n8.x4.shared.b16 {%0,%1,%2,%3}, [%4];"
                 : "=r"(r[0]), "=r"(r[1]), "=r"(r[2]), "=r"(r[3]) : "r"(addr));
}
__device__ __forceinline__ void cp16(uint32_t dst, const void* src) {
    asm volatile("cp.async.cg.shared.global [%0], [%1], 16;" :: "r"(dst), "l"(src));
}
#define CP_COMMIT() asm volatile("cp.async.commit_group;")
#define CP_WAIT1()  asm volatile("cp.async.wait_group 1;")
#define CP_WAIT0()  asm volatile("cp.async.wait_group 0;")

// ---- prep: tiled transposes (coalesced both sides) ----
__global__ void prep_w1t_kernel(const float* __restrict__ W1, __half* __restrict__ w1t) {
    __shared__ float tile[32][33];
    int bx = blockIdx.x, by = blockIdx.y;
    int x = threadIdx.x, y = threadIdx.y;
    #pragma unroll
    for (int j = 0; j < 4; j++) {
        int k = by * 32 + y + j * 8;
        tile[y + j * 8][x] = (k < 300) ? W1[(size_t)k * HID + bx * 32 + x] : 0.0f;
    }
    __syncthreads();
    #pragma unroll
    for (int j = 0; j < 4; j++) {
        int n = bx * 32 + y + j * 8;
        w1t[(size_t)n * KF + by * 32 + x] = __float2half(tile[x][y + j * 8]);
    }
}
__global__ void prep_w2t_kernel(const float* __restrict__ W2, __half* __restrict__ w2t) {
    __shared__ float tile[32][33];
    int bx = blockIdx.x, by = blockIdx.y;
    int x = threadIdx.x, y = threadIdx.y;
    #pragma unroll
    for (int j = 0; j < 4; j++)
        tile[y + j * 8][x] = W2[(size_t)(by * 32 + y + j * 8) * HID + bx * 32 + x];
    __syncthreads();
    #pragma unroll
    for (int j = 0; j < 4; j++)
        w2t[(size_t)(bx * 32 + y + j * 8) * HID + by * 32 + x] =
            __float2half(tile[x][y + j * 8]);
}

// ---- init output with b3 (precedes gemm2 only) ----
__global__ void init_out_kernel(float* __restrict__ out, const float* __restrict__ b3) {
    int i = blockIdx.x * blockDim.x + threadIdx.x;
    if (i < BSZ) out[i] = b3[0];
}

// ---- features: 320 threads / 32 rows per block; smem-staged, fully coalesced ----
// Packs E into half2 locally (no separate prep dependency).
#define FROWS 32
#define FTHREADS (FROWS * TTR)           // 320
__global__ void __launch_bounds__(FTHREADS) feat_kernel(
    const float* __restrict__ structures, const float* __restrict__ E,
    __half* __restrict__ feat) {
    __shared__ uint32_t sEu[NUM_ELEM * 5];
    __shared__ __align__(16) float    sS[FROWS * 30];   // staged structures
    __shared__ __align__(16) uint32_t sF[FROWS * 160];  // staged output rows

    int tid = threadIdx.x;
    for (int i = tid; i < NUM_ELEM * 5; i += FTHREADS) {
        int n = i / 5, c = i - n * 5;
        __half2 h = __floats2half2_rn(E[n * 10 + 2 * c], E[n * 10 + 2 * c + 1]);
        sEu[i] = *(uint32_t*)&h;
    }

    size_t base_row = (size_t)blockIdx.x * FROWS;
    #pragma unroll
    for (int i = 0; i < 3; i++)
        sS[tid + i * FTHREADS] = structures[base_row * 30 + tid + i * FTHREADS];
    __syncthreads();

    int r = tid / TTR;
    int t = tid - r * TTR;

    float s0 = sS[r * 30 + t * 3];
    float s1 = sS[r * 30 + t * 3 + 1];
    float d  = sS[r * 30 + t * 3 + 2];
    int ii = (int)s0;
    int jj = (int)s1;

    uint32_t* o = &sF[r * 160 + t * 15];
    #pragma unroll
    for (int c = 0; c < 5; c++) o[c] = ii ? sEu[ii * 5 + c] : 0u;
    #pragma unroll
    for (int c = 0; c < 5; c++) o[5 + c] = jj ? sEu[jj * 5 + c] : 0u;

    // RBF recurrence: 2 MUFU per triplet
    float rb[10];
    float df = 0.7f - d;
    float rv = __expf(-df * df);
    float f  = __expf(1.4f * d - 1.47f);
    rb[0] = rv;
    #pragma unroll
    for (int c = 1; c < 10; c++) {
        rv *= f;
        rb[c] = rv;
        f *= 0.37531110f;         // exp(-0.98)
    }
    if (!ii) {
        #pragma unroll
        for (int c = 0; c < 10; c++) rb[c] = 0.0f;
    }
    #pragma unroll
    for (int p = 0; p < 5; p++) {
        __half2 h = __floats2half2_rn(rb[2 * p], rb[2 * p + 1]);
        o[10 + p] = *(uint32_t*)&h;
    }
    if (t == 0) {
        #pragma unroll
        for (int p = 0; p < 10; p++) sF[r * 160 + 150 + p] = 0u;
    }
    __syncthreads();

    const uint4* src = (const uint4*)sF;
    uint4* dst = (uint4*)(feat + base_row * KF);
    #pragma unroll
    for (int i = 0; i < 4; i++)
        dst[tid + i * FTHREADS] = src[tid + i * FTHREADS];
}

// ---- fp16 GEMM: BM=BN=128, warp 32x64, 2 CTAs/SM, 3-stage, reg-pipelined ----
// (UNCHANGED from Round 11 best — do not touch)
#define BM 128
#define BN 128
#define BK 64
#define RSTR 144
#define ASTAGE (BM * RSTR)
#define BSTAGE (BN * RSTR)
#define STAGE (ASTAGE + BSTAGE)
#define NSTG 3
#define SMEM_BYTES (NSTG * STAGE + 2 * BN * 4)

template <int EPI>
__global__ void __launch_bounds__(256, 2) gemm_kernel(
    const __half* __restrict__ A, int lda, int K,
    const __half* __restrict__ Bt,
    const float* __restrict__ bias,
    const float* __restrict__ W3,
    void* __restrict__ CoutV)
{
    extern __shared__ char smem[];
    uint32_t sbase;
    asm("{ .reg .u64 t; cvta.to.shared.u64 t, %1; cvt.u32.u64 %0, t; }"
        : "=r"(sbase) : "l"(smem));
    float* sBias = (float*)(smem + NSTG * STAGE);
    float* sW3   = sBias + BN;

    const int tid  = threadIdx.x;
    const int lane = tid & 31;
    const int wid  = tid >> 5;
    const int wm   = wid & 3;
    const int wn   = wid >> 2;
    const int g    = lane >> 2;
    const int t    = lane & 3;
    const int lr   = lane & 7;
    const int m0   = blockIdx.y * BM;
    const int n0   = blockIdx.x * BN;

    float acc[2][8][4];
    #pragma unroll
    for (int i = 0; i < 2; i++)
        #pragma unroll
        for (int j = 0; j < 8; j++)
            #pragma unroll
            for (int k = 0; k < 4; k++) acc[i][j][k] = 0.0f;

    const int KT = K / BK;

    auto issue = [&](int kt, int buf) {
        int k0 = kt * BK;
        uint32_t ab = sbase + buf * STAGE;
        uint32_t bb = ab + ASTAGE;
        #pragma unroll
        for (int i = 0; i < 4; i++) {
            int idx = tid + (i << 8);
            int row = idx >> 3, c = idx & 7;
            cp16(ab + row * RSTR + c * 16,
                 A + (size_t)(m0 + row) * lda + k0 + c * 8);
        }
        #pragma unroll
        for (int i = 0; i < 4; i++) {
            int idx = tid + (i << 8);
            int row = idx >> 3, c = idx & 7;
            cp16(bb + row * RSTR + c * 16,
                 Bt + (size_t)(n0 + row) * K + k0 + c * 8);
        }
    };

    auto compute = [&](int buf) {
        uint32_t ab = sbase + buf * STAGE;
        uint32_t bb = ab + ASTAGE;

        auto lda_ = [&](uint32_t* r, int ms, int ks) {
            int row = wm * 32 + ms * 16 + lr + ((lane >> 3) & 1) * 8;
            int ch  = ks * 2 + (lane >> 4);
            ldsm4(r, ab + row * RSTR + ch * 16);
        };
        auto ldb_ = [&](uint32_t* r, int np, int ks) {
            int row = wn * 64 + np * 16 + lr + (lane >> 4) * 8;
            int ch  = ks * 2 + ((lane >> 3) & 1);
            ldsm4(r, bb + row * RSTR + ch * 16);
        };

        uint32_t a[2][4], an[2][4];
        uint32_t bc[4], bn[4];

        lda_(a[0], 0, 0); lda_(a[1], 1, 0);
        ldb_(bc, 0, 0);

        #pragma unroll
        for (int ks = 0; ks < 4; ks++) {
            #pragma unroll
            for (int np = 0; np < 4; np++) {
                if (np < 3)            ldb_(bn, np + 1, ks);
                else if (ks < 3)       ldb_(bn, 0, ks + 1);
                if (np == 0 && ks < 3) { lda_(an[0], 0, ks + 1); lda_(an[1], 1, ks + 1); }

                mma16(acc[0][2 * np],     a[0], bc[0], bc[1]);
                mma16(acc[0][2 * np + 1], a[0], bc[2], bc[3]);
                mma16(acc[1][2 * np],     a[1], bc[0], bc[1]);
                mma16(acc[1][2 * np + 1], a[1], bc[2], bc[3]);

                if (!(ks == 3 && np == 3)) {
                    bc[0] = bn[0]; bc[1] = bn[1]; bc[2] = bn[2]; bc[3] = bn[3];
                }
            }
            if (ks < 3) {
                #pragma unroll
                for (int q = 0; q < 4; q++) { a[0][q] = an[0][q]; a[1][q] = an[1][q]; }
            }
        }
    };

    issue(0, 0); CP_COMMIT();
    issue(1, 1); CP_COMMIT();

    for (int kt = 0; kt < KT; kt++) {
        int cur = kt - (kt / NSTG) * NSTG;
        if (kt + 1 < KT) CP_WAIT1(); else CP_WAIT0();
        __syncthreads();
        if (kt + 2 < KT) {
            int nb = kt + 2;
            issue(nb, nb - (nb / NSTG) * NSTG);
            CP_COMMIT();
        }
        compute(cur);
    }

    for (int i = tid; i < BN; i += 256) {
        sBias[i] = bias[n0 + i];
        if (EPI == 1) sW3[i] = W3[n0 + i];
    }
    __syncthreads();

    if (EPI == 0) {
        __half* Cout = (__half*)CoutV;
        #pragma unroll
        for (int ms = 0; ms < 2; ms++) {
            int row = m0 + wm * 32 + ms * 16 + g;
            #pragma unroll
            for (int ns = 0; ns < 8; ns++) {
                int cl  = wn * 64 + ns * 8 + t * 2;
                int col = n0 + cl;
                __half2 v0 = __floats2half2_rn(
                    fmaxf(acc[ms][ns][0] + sBias[cl],     0.0f),
                    fmaxf(acc[ms][ns][1] + sBias[cl + 1], 0.0f));
                __half2 v1 = __floats2half2_rn(
                    fmaxf(acc[ms][ns][2] + sBias[cl],     0.0f),
                    fmaxf(acc[ms][ns][3] + sBias[cl + 1], 0.0f));
                *(__half2*)&Cout[(size_t)row * HID + col]       = v0;
                *(__half2*)&Cout[(size_t)(row + 8) * HID + col] = v1;
            }
        }
    } else {
        float* Cout = (float*)CoutV;
        float racc[2][2] = {{0.0f, 0.0f}, {0.0f, 0.0f}};
        #pragma unroll
        for (int ms = 0; ms < 2; ms++) {
            #pragma unroll
            for (int ns = 0; ns < 8; ns++) {
                int cl = wn * 64 + ns * 8 + t * 2;
                racc[ms][0] += fmaxf(acc[ms][ns][0] + sBias[cl],     0.0f) * sW3[cl]
                             + fmaxf(acc[ms][ns][1] + sBias[cl + 1], 0.0f) * sW3[cl + 1];
                racc[ms][1] += fmaxf(acc[ms][ns][2] + sBias[cl],     0.0f) * sW3[cl]
                             + fmaxf(acc[ms][ns][3] + sBias[cl + 1], 0.0f) * sW3[cl + 1];
            }
        }
        #pragma unroll
        for (int ms = 0; ms < 2; ms++) {
            #pragma unroll
            for (int rp = 0; rp < 2; rp++) {
                float p = racc[ms][rp];
                p += __shfl_xor_sync(0xffffffffu, p, 1);
                p += __shfl_xor_sync(0xffffffffu, p, 2);
                if (t == 0)
                    atomicAdd(&Cout[m0 + wm * 32 + ms * 16 + rp * 8 + g], p);
            }
        }
    }
}

// ---- launch (order chosen so gemm_kernel<0> sits at launch index 3 for ncu) ----
extern "C" void kernel_launch(void* const* d_in, const int* in_sizes, int n_in,
                              void* d_out, int out_size) {
    const float* structures = (const float*)d_in[0];
    const float* E  = (const float*)d_in[1];
    const float* W1 = (const float*)d_in[2];
    const float* b1 = (const float*)d_in[3];
    const float* W2 = (const float*)d_in[4];
    const float* b2 = (const float*)d_in[5];
    const float* W3 = (const float*)d_in[6];
    const float* b3 = (const float*)d_in[7];
    float* out = (float*)d_out;

    __half *feat, *h1, *w1t, *w2t;
    cudaGetSymbolAddress((void**)&feat, g_feat);
    cudaGetSymbolAddress((void**)&h1,   g_h1);
    cudaGetSymbolAddress((void**)&w1t,  g_w1t);
    cudaGetSymbolAddress((void**)&w2t,  g_w2t);

    cudaFuncSetAttribute(gemm_kernel<0>, cudaFuncAttributeMaxDynamicSharedMemorySize, SMEM_BYTES);
    cudaFuncSetAttribute(gemm_kernel<1>, cudaFuncAttributeMaxDynamicSharedMemorySize, SMEM_BYTES);

    dim3 grid(HID / BN, BSZ / BM);   // (8, 1024)

    prep_w2t_kernel<<<dim3(32, 32), dim3(32, 8)>>>(W2, w2t);           // idx 0
    prep_w1t_kernel<<<dim3(32, 10), dim3(32, 8)>>>(W1, w1t);           // idx 1
    feat_kernel<<<BSZ / FROWS, FTHREADS>>>(structures, E, feat);       // idx 2
    gemm_kernel<0><<<grid, 256, SMEM_BYTES>>>(feat, KF, KF, w1t, b1,   // idx 3 (profiled)
                                              nullptr, (void*)h1);
    init_out_kernel<<<(BSZ + 255) / 256, 256>>>(out, b3);              // idx 4
    gemm_kernel<1><<<grid, 256, SMEM_BYTES>>>(h1, HID, HID, w2t, b2,   // idx 5
                                              W3, (void*)out);
}

// round 16
// speedup vs baseline: 1.0136x; 1.0136x over previous
#include <cuda_runtime.h>
#include <cuda_fp16.h>
#include <math.h>
#include <stdint.h>

#define BSZ 131072
#define TTR 10
#define KF 320          // padded feature dim (300 -> 320)
#define HID 1024
#define NUM_ELEM 118

// ---- scratch (device globals; no runtime allocation) ----
__device__ __half g_feat[(size_t)BSZ * KF];
__device__ __half g_h1[(size_t)BSZ * HID];
__device__ __half g_w1t[(size_t)HID * KF];    // W1^T [n][k], zero-padded
__device__ __half g_w2t[(size_t)HID * HID];   // W2^T [n][k]

// ---- helpers ----
__device__ __forceinline__ void mma16(float* c, const uint32_t* a,
                                      uint32_t b0, uint32_t b1) {
    asm volatile(
        "mma.sync.aligned.m16n8k16.row.col.f32.f16.f16.f32 "
        "{%0,%1,%2,%3}, {%4,%5,%6,%7}, {%8,%9}, {%0,%1,%2,%3};"
        : "+f"(c[0]), "+f"(c[1]), "+f"(c[2]), "+f"(c[3])
        : "r"(a[0]), "r"(a[1]), "r"(a[2]), "r"(a[3]), "r"(b0), "r"(b1));
}
__device__ __forceinline__ void ldsm4(uint32_t* r, uint32_t addr) {
    asm volatile("ldmatrix.sync.aligned.m8n8.x4.shared.b16 {%0,%1,%2,%3}, [%4];"
                 : "=r"(r[0]), "=r"(r[1]), "=r"(r[2]), "=r"(r[3]) : "r"(addr));
}
__device__ __forceinline__ void cp16(uint32_t dst, const void* src) {
    asm volatile("cp.async.cg.shared.global [%0], [%1], 16;" :: "r"(dst), "l"(src));
}
#define CP_COMMIT() asm volatile("cp.async.commit_group;")
#define CP_WAIT1()  asm volatile("cp.async.wait_group 1;")
#define CP_WAIT0()  asm volatile("cp.async.wait_group 0;")

// ---- prep_all: w2t tiles [0,1024) | w1t tiles [1024,1344) | out-init [1344,1856) ----
__global__ void prep_all_kernel(const float* __restrict__ W1,
                                const float* __restrict__ W2,
                                const float* __restrict__ b3,
                                float* __restrict__ out,
                                __half* __restrict__ w1t,
                                __half* __restrict__ w2t) {
    __shared__ float tile[32][33];
    int bid = blockIdx.x;
    int x = threadIdx.x, y = threadIdx.y;     // 32 x 8

    if (bid < 1024) {                          // w2t transpose tile
        int bx = bid & 31, by = bid >> 5;
        #pragma unroll
        for (int j = 0; j < 4; j++)
            tile[y + j * 8][x] = W2[(size_t)(by * 32 + y + j * 8) * HID + bx * 32 + x];
        __syncthreads();
        #pragma unroll
        for (int j = 0; j < 4; j++)
            w2t[(size_t)(bx * 32 + y + j * 8) * HID + by * 32 + x] =
                __float2half(tile[x][y + j * 8]);
    } else if (bid < 1344) {                   // w1t transpose tile (10 k-tiles)
        int b = bid - 1024;
        int bx = b & 31, by = b >> 5;
        #pragma unroll
        for (int j = 0; j < 4; j++) {
            int k = by * 32 + y + j * 8;
            tile[y + j * 8][x] = (k < 300) ? W1[(size_t)k * HID + bx * 32 + x] : 0.0f;
        }
        __syncthreads();
        #pragma unroll
        for (int j = 0; j < 4; j++) {
            int n = bx * 32 + y + j * 8;
            w1t[(size_t)n * KF + by * 32 + x] = __float2half(tile[x][y + j * 8]);
        }
    } else {                                   // out init with b3
        int i = (bid - 1344) * 256 + y * 32 + x;
        if (i < BSZ) out[i] = b3[0];
    }
}

// ---- features: 320 threads / 32 rows per block; smem-staged, fully coalesced ----
#define FROWS 32
#define FTHREADS (FROWS * TTR)           // 320
__global__ void __launch_bounds__(FTHREADS) feat_kernel(
    const float* __restrict__ structures, const float* __restrict__ E,
    __half* __restrict__ feat) {
    __shared__ uint32_t sEu[NUM_ELEM * 5];
    __shared__ __align__(16) float    sS[FROWS * 30];
    __shared__ __align__(16) uint32_t sF[FROWS * 160];

    int tid = threadIdx.x;
    for (int i = tid; i < NUM_ELEM * 5; i += FTHREADS) {
        int n = i / 5, c = i - n * 5;
        __half2 h = __floats2half2_rn(E[n * 10 + 2 * c], E[n * 10 + 2 * c + 1]);
        sEu[i] = *(uint32_t*)&h;
    }

    size_t base_row = (size_t)blockIdx.x * FROWS;
    #pragma unroll
    for (int i = 0; i < 3; i++)
        sS[tid + i * FTHREADS] = structures[base_row * 30 + tid + i * FTHREADS];
    __syncthreads();

    int r = tid / TTR;
    int t = tid - r * TTR;

    float s0 = sS[r * 30 + t * 3];
    float s1 = sS[r * 30 + t * 3 + 1];
    float d  = sS[r * 30 + t * 3 + 2];
    int ii = (int)s0;
    int jj = (int)s1;

    uint32_t* o = &sF[r * 160 + t * 15];
    #pragma unroll
    for (int c = 0; c < 5; c++) o[c] = ii ? sEu[ii * 5 + c] : 0u;
    #pragma unroll
    for (int c = 0; c < 5; c++) o[5 + c] = jj ? sEu[jj * 5 + c] : 0u;

    float rb[10];
    float df = 0.7f - d;
    float rv = __expf(-df * df);
    float f  = __expf(1.4f * d - 1.47f);
    rb[0] = rv;
    #pragma unroll
    for (int c = 1; c < 10; c++) {
        rv *= f;
        rb[c] = rv;
        f *= 0.37531110f;         // exp(-0.98)
    }
    if (!ii) {
        #pragma unroll
        for (int c = 0; c < 10; c++) rb[c] = 0.0f;
    }
    #pragma unroll
    for (int p = 0; p < 5; p++) {
        __half2 h = __floats2half2_rn(rb[2 * p], rb[2 * p + 1]);
        o[10 + p] = *(uint32_t*)&h;
    }
    if (t == 0) {
        #pragma unroll
        for (int p = 0; p < 10; p++) sF[r * 160 + 150 + p] = 0u;
    }
    __syncthreads();

    const uint4* src = (const uint4*)sF;
    uint4* dst = (uint4*)(feat + base_row * KF);
    #pragma unroll
    for (int i = 0; i < 4; i++)
        dst[tid + i * FTHREADS] = src[tid + i * FTHREADS];
}

// ---- fp16 GEMM: BM=BN=128, warp 32x64, 2 CTAs/SM, 3-stage, reg-pipelined ----
// Mainloop frozen (R11). Only change: bias/W3 staged BEFORE mainloop.
#define BM 128
#define BN 128
#define BK 64
#define RSTR 144
#define ASTAGE (BM * RSTR)
#define BSTAGE (BN * RSTR)
#define STAGE (ASTAGE + BSTAGE)
#define NSTG 3
#define SMEM_BYTES (NSTG * STAGE + 2 * BN * 4)

template <int EPI>
__global__ void __launch_bounds__(256, 2) gemm_kernel(
    const __half* __restrict__ A, int lda, int K,
    const __half* __restrict__ Bt,
    const float* __restrict__ bias,
    const float* __restrict__ W3,
    void* __restrict__ CoutV)
{
    extern __shared__ char smem[];
    uint32_t sbase;
    asm("{ .reg .u64 t; cvta.to.shared.u64 t, %1; cvt.u32.u64 %0, t; }"
        : "=r"(sbase) : "l"(smem));
    float* sBias = (float*)(smem + NSTG * STAGE);
    float* sW3   = sBias + BN;

    const int tid  = threadIdx.x;
    const int lane = tid & 31;
    const int wid  = tid >> 5;
    const int wm   = wid & 3;
    const int wn   = wid >> 2;
    const int g    = lane >> 2;
    const int t    = lane & 3;
    const int lr   = lane & 7;
    const int m0   = blockIdx.y * BM;
    const int n0   = blockIdx.x * BN;

    float acc[2][8][4];
    #pragma unroll
    for (int i = 0; i < 2; i++)
        #pragma unroll
        for (int j = 0; j < 8; j++)
            #pragma unroll
            for (int k = 0; k < 4; k++) acc[i][j][k] = 0.0f;

    const int KT = K / BK;

    auto issue = [&](int kt, int buf) {
        int k0 = kt * BK;
        uint32_t ab = sbase + buf * STAGE;
        uint32_t bb = ab + ASTAGE;
        #pragma unroll
        for (int i = 0; i < 4; i++) {
            int idx = tid + (i << 8);
            int row = idx >> 3, c = idx & 7;
            cp16(ab + row * RSTR + c * 16,
                 A + (size_t)(m0 + row) * lda + k0 + c * 8);
        }
        #pragma unroll
        for (int i = 0; i < 4; i++) {
            int idx = tid + (i << 8);
            int row = idx >> 3, c = idx & 7;
            cp16(bb + row * RSTR + c * 16,
                 Bt + (size_t)(n0 + row) * K + k0 + c * 8);
        }
    };

    auto compute = [&](int buf) {
        uint32_t ab = sbase + buf * STAGE;
        uint32_t bb = ab + ASTAGE;

        auto lda_ = [&](uint32_t* r, int ms, int ks) {
            int row = wm * 32 + ms * 16 + lr + ((lane >> 3) & 1) * 8;
            int ch  = ks * 2 + (lane >> 4);
            ldsm4(r, ab + row * RSTR + ch * 16);
        };
        auto ldb_ = [&](uint32_t* r, int np, int ks) {
            int row = wn * 64 + np * 16 + lr + (lane >> 4) * 8;
            int ch  = ks * 2 + ((lane >> 3) & 1);
            ldsm4(r, bb + row * RSTR + ch * 16);
        };

        uint32_t a[2][4], an[2][4];
        uint32_t bc[4], bn[4];

        lda_(a[0], 0, 0); lda_(a[1], 1, 0);
        ldb_(bc, 0, 0);

        #pragma unroll
        for (int ks = 0; ks < 4; ks++) {
            #pragma unroll
            for (int np = 0; np < 4; np++) {
                if (np < 3)            ldb_(bn, np + 1, ks);
                else if (ks < 3)       ldb_(bn, 0, ks + 1);
                if (np == 0 && ks < 3) { lda_(an[0], 0, ks + 1); lda_(an[1], 1, ks + 1); }

                mma16(acc[0][2 * np],     a[0], bc[0], bc[1]);
                mma16(acc[0][2 * np + 1], a[0], bc[2], bc[3]);
                mma16(acc[1][2 * np],     a[1], bc[0], bc[1]);
                mma16(acc[1][2 * np + 1], a[1], bc[2], bc[3]);

                if (!(ks == 3 && np == 3)) {
                    bc[0] = bn[0]; bc[1] = bn[1]; bc[2] = bn[2]; bc[3] = bn[3];
                }
            }
            if (ks < 3) {
                #pragma unroll
                for (int q = 0; q < 4; q++) { a[0][q] = an[0][q]; a[1][q] = an[1][q]; }
            }
        }
    };

    issue(0, 0); CP_COMMIT();
    issue(1, 1); CP_COMMIT();

    // bias/W3 staged early (disjoint smem; mainloop syncs order it before epilogue)
    for (int i = tid; i < BN; i += 256) {
        sBias[i] = bias[n0 + i];
        if (EPI == 1) sW3[i] = W3[n0 + i];
    }

    for (int kt = 0; kt < KT; kt++) {
        int cur = kt - (kt / NSTG) * NSTG;
        if (kt + 1 < KT) CP_WAIT1(); else CP_WAIT0();
        __syncthreads();
        if (kt + 2 < KT) {
            int nb = kt + 2;
            issue(nb, nb - (nb / NSTG) * NSTG);
            CP_COMMIT();
        }
        compute(cur);
    }

    if (EPI == 0) {
        __half* Cout = (__half*)CoutV;
        #pragma unroll
        for (int ms = 0; ms < 2; ms++) {
            int row = m0 + wm * 32 + ms * 16 + g;
            #pragma unroll
            for (int ns = 0; ns < 8; ns++) {
                int cl  = wn * 64 + ns * 8 + t * 2;
                int col = n0 + cl;
                __half2 v0 = __floats2half2_rn(
                    fmaxf(acc[ms][ns][0] + sBias[cl],     0.0f),
                    fmaxf(acc[ms][ns][1] + sBias[cl + 1], 0.0f));
                __half2 v1 = __floats2half2_rn(
                    fmaxf(acc[ms][ns][2] + sBias[cl],     0.0f),
                    fmaxf(acc[ms][ns][3] + sBias[cl + 1], 0.0f));
                *(__half2*)&Cout[(size_t)row * HID + col]       = v0;
                *(__half2*)&Cout[(size_t)(row + 8) * HID + col] = v1;
            }
        }
    } else {
        float* Cout = (float*)CoutV;
        float racc[2][2] = {{0.0f, 0.0f}, {0.0f, 0.0f}};
        #pragma unroll
        for (int ms = 0; ms < 2; ms++) {
            #pragma unroll
            for (int ns = 0; ns < 8; ns++) {
                int cl = wn * 64 + ns * 8 + t * 2;
                racc[ms][0] += fmaxf(acc[ms][ns][0] + sBias[cl],     0.0f) * sW3[cl]
                             + fmaxf(acc[ms][ns][1] + sBias[cl + 1], 0.0f) * sW3[cl + 1];
                racc[ms][1] += fmaxf(acc[ms][ns][2] + sBias[cl],     0.0f) * sW3[cl]
                             + fmaxf(acc[ms][ns][3] + sBias[cl + 1], 0.0f) * sW3[cl + 1];
            }
        }
        #pragma unroll
        for (int ms = 0; ms < 2; ms++) {
            #pragma unroll
            for (int rp = 0; rp < 2; rp++) {
                float p = racc[ms][rp];
                p += __shfl_xor_sync(0xffffffffu, p, 1);
                p += __shfl_xor_sync(0xffffffffu, p, 2);
                if (t == 0)
                    atomicAdd(&Cout[m0 + wm * 32 + ms * 16 + rp * 8 + g], p);
            }
        }
    }
}

// ---- launch: 4 kernels; gemm2 at index 3 (profiled) ----
extern "C" void kernel_launch(void* const* d_in, const int* in_sizes, int n_in,
                              void* d_out, int out_size) {
    const float* structures = (const float*)d_in[0];
    const float* E  = (const float*)d_in[1];
    const float* W1 = (const float*)d_in[2];
    const float* b1 = (const float*)d_in[3];
    const float* W2 = (const float*)d_in[4];
    const float* b2 = (const float*)d_in[5];
    const float* W3 = (const float*)d_in[6];
    const float* b3 = (const float*)d_in[7];
    float* out = (float*)d_out;

    __half *feat, *h1, *w1t, *w2t;
    cudaGetSymbolAddress((void**)&feat, g_feat);
    cudaGetSymbolAddress((void**)&h1,   g_h1);
    cudaGetSymbolAddress((void**)&w1t,  g_w1t);
    cudaGetSymbolAddress((void**)&w2t,  g_w2t);

    cudaFuncSetAttribute(gemm_kernel<0>, cudaFuncAttributeMaxDynamicSharedMemorySize, SMEM_BYTES);
    cudaFuncSetAttribute(gemm_kernel<1>, cudaFuncAttributeMaxDynamicSharedMemorySize, SMEM_BYTES);

    dim3 grid(HID / BN, BSZ / BM);   // (8, 1024)

    prep_all_kernel<<<1856, dim3(32, 8)>>>(W1, W2, b3, out, w1t, w2t);   // idx 0
    feat_kernel<<<BSZ / FROWS, FTHREADS>>>(structures, E, feat);         // idx 1
    gemm_kernel<0><<<grid, 256, SMEM_BYTES>>>(feat, KF, KF, w1t, b1,     // idx 2
                                              nullptr, (void*)h1);
    gemm_kernel<1><<<grid, 256, SMEM_BYTES>>>(h1, HID, HID, w2t, b2,     // idx 3 (profiled)
                                              W3, (void*)out);
}

// round 17
// speedup vs baseline: 1.1360x; 1.1208x over previous
#include <cuda_runtime.h>
#include <cuda_fp16.h>
#include <math.h>
#include <stdint.h>

#define BSZ 131072
#define TTR 10
#define KF 320          // padded feature dim (300 -> 320)
#define HID 1024
#define NUM_ELEM 118

// ---- scratch (device globals; no runtime allocation) ----
__device__ __half g_feat[(size_t)BSZ * KF];
__device__ __half g_h1[(size_t)BSZ * HID];
__device__ __half g_w1t[(size_t)HID * KF];    // W1^T [n][k], zero-padded
__device__ __half g_w2t[(size_t)HID * HID];   // W2^T [n][k]

// ---- helpers ----
__device__ __forceinline__ void mma16(float* c, const uint32_t* a,
                                      uint32_t b0, uint32_t b1) {
    asm volatile(
        "mma.sync.aligned.m16n8k16.row.col.f32.f16.f16.f32 "
        "{%0,%1,%2,%3}, {%4,%5,%6,%7}, {%8,%9}, {%0,%1,%2,%3};"
        : "+f"(c[0]), "+f"(c[1]), "+f"(c[2]), "+f"(c[3])
        : "r"(a[0]), "r"(a[1]), "r"(a[2]), "r"(a[3]), "r"(b0), "r"(b1));
}
__device__ __forceinline__ void ldsm4(uint32_t* r, uint32_t addr) {
    asm volatile("ldmatrix.sync.aligned.m8n8.x4.shared.b16 {%0,%1,%2,%3}, [%4];"
                 : "=r"(r[0]), "=r"(r[1]), "=r"(r[2]), "=r"(r[3]) : "r"(addr));
}
__device__ __forceinline__ void cp16(uint32_t dst, const void* src) {
    asm volatile("cp.async.cg.shared.global [%0], [%1], 16;" :: "r"(dst), "l"(src));
}
#define CP_COMMIT() asm volatile("cp.async.commit_group;")
#define CP_WAIT1()  asm volatile("cp.async.wait_group 1;")
#define CP_WAIT0()  asm volatile("cp.async.wait_group 0;")

// ---- prep_all: w2t tiles [0,1024) | w1t tiles [1024,1344) | out-init [1344,1856) ----
__global__ void prep_all_kernel(const float* __restrict__ W1,
                                const float* __restrict__ W2,
                                const float* __restrict__ b3,
                                float* __restrict__ out,
                                __half* __restrict__ w1t,
                                __half* __restrict__ w2t) {
    __shared__ float tile[32][33];
    int bid = blockIdx.x;
    int x = threadIdx.x, y = threadIdx.y;     // 32 x 8

    if (bid < 1024) {
        int bx = bid & 31, by = bid >> 5;
        #pragma unroll
        for (int j = 0; j < 4; j++)
            tile[y + j * 8][x] = W2[(size_t)(by * 32 + y + j * 8) * HID + bx * 32 + x];
        __syncthreads();
        #pragma unroll
        for (int j = 0; j < 4; j++)
            w2t[(size_t)(bx * 32 + y + j * 8) * HID + by * 32 + x] =
                __float2half(tile[x][y + j * 8]);
    } else if (bid < 1344) {
        int b = bid - 1024;
        int bx = b & 31, by = b >> 5;
        #pragma unroll
        for (int j = 0; j < 4; j++) {
            int k = by * 32 + y + j * 8;
            tile[y + j * 8][x] = (k < 300) ? W1[(size_t)k * HID + bx * 32 + x] : 0.0f;
        }
        __syncthreads();
        #pragma unroll
        for (int j = 0; j < 4; j++) {
            int n = bx * 32 + y + j * 8;
            w1t[(size_t)n * KF + by * 32 + x] = __float2half(tile[x][y + j * 8]);
        }
    } else {
        int i = (bid - 1344) * 256 + y * 32 + x;
        if (i < BSZ) out[i] = b3[0];
    }
}

// ---- features: 320 threads / 32 rows per block; smem-staged, fully coalesced ----
#define FROWS 32
#define FTHREADS (FROWS * TTR)           // 320
__global__ void __launch_bounds__(FTHREADS) feat_kernel(
    const float* __restrict__ structures, const float* __restrict__ E,
    __half* __restrict__ feat) {
    __shared__ uint32_t sEu[NUM_ELEM * 5];
    __shared__ __align__(16) float    sS[FROWS * 30];
    __shared__ __align__(16) uint32_t sF[FROWS * 160];

    int tid = threadIdx.x;
    for (int i = tid; i < NUM_ELEM * 5; i += FTHREADS) {
        int n = i / 5, c = i - n * 5;
        __half2 h = __floats2half2_rn(E[n * 10 + 2 * c], E[n * 10 + 2 * c + 1]);
        sEu[i] = *(uint32_t*)&h;
    }

    size_t base_row = (size_t)blockIdx.x * FROWS;
    #pragma unroll
    for (int i = 0; i < 3; i++)
        sS[tid + i * FTHREADS] = structures[base_row * 30 + tid + i * FTHREADS];
    __syncthreads();

    int r = tid / TTR;
    int t = tid - r * TTR;

    float s0 = sS[r * 30 + t * 3];
    float s1 = sS[r * 30 + t * 3 + 1];
    float d  = sS[r * 30 + t * 3 + 2];
    int ii = (int)s0;
    int jj = (int)s1;

    uint32_t* o = &sF[r * 160 + t * 15];
    #pragma unroll
    for (int c = 0; c < 5; c++) o[c] = ii ? sEu[ii * 5 + c] : 0u;
    #pragma unroll
    for (int c = 0; c < 5; c++) o[5 + c] = jj ? sEu[jj * 5 + c] : 0u;

    float rb[10];
    float df = 0.7f - d;
    float rv = __expf(-df * df);
    float f  = __expf(1.4f * d - 1.47f);
    rb[0] = rv;
    #pragma unroll
    for (int c = 1; c < 10; c++) {
        rv *= f;
        rb[c] = rv;
        f *= 0.37531110f;         // exp(-0.98)
    }
    if (!ii) {
        #pragma unroll
        for (int c = 0; c < 10; c++) rb[c] = 0.0f;
    }
    #pragma unroll
    for (int p = 0; p < 5; p++) {
        __half2 h = __floats2half2_rn(rb[2 * p], rb[2 * p + 1]);
        o[10 + p] = *(uint32_t*)&h;
    }
    if (t == 0) {
        #pragma unroll
        for (int p = 0; p < 10; p++) sF[r * 160 + 150 + p] = 0u;
    }
    __syncthreads();

    const uint4* src = (const uint4*)sF;
    uint4* dst = (uint4*)(feat + base_row * KF);
    #pragma unroll
    for (int i = 0; i < 4; i++)
        dst[tid + i * FTHREADS] = src[tid + i * FTHREADS];
}

// ---- fp16 GEMM: BM=BN=128, warp 32x64, 2 CTAs/SM, 3-stage ----
// cp.async issue for tile kt+2 interleaved INTO compute(kt)'s mma stream.
#define BM 128
#define BN 128
#define BK 64
#define RSTR 144
#define ASTAGE (BM * RSTR)
#define BSTAGE (BN * RSTR)
#define STAGE (ASTAGE + BSTAGE)
#define NSTG 3
#define SMEM_BYTES (NSTG * STAGE + 2 * BN * 4)

template <int EPI>
__global__ void __launch_bounds__(256, 2) gemm_kernel(
    const __half* __restrict__ A, int lda, int K,
    const __half* __restrict__ Bt,
    const float* __restrict__ bias,
    const float* __restrict__ W3,
    void* __restrict__ CoutV)
{
    extern __shared__ char smem[];
    uint32_t sbase;
    asm("{ .reg .u64 t; cvta.to.shared.u64 t, %1; cvt.u32.u64 %0, t; }"
        : "=r"(sbase) : "l"(smem));
    float* sBias = (float*)(smem + NSTG * STAGE);
    float* sW3   = sBias + BN;

    const int tid  = threadIdx.x;
    const int lane = tid & 31;
    const int wid  = tid >> 5;
    const int wm   = wid & 3;
    const int wn   = wid >> 2;
    const int g    = lane >> 2;
    const int t    = lane & 3;
    const int lr   = lane & 7;
    const int m0   = blockIdx.y * BM;
    const int n0   = blockIdx.x * BN;

    float acc[2][8][4];
    #pragma unroll
    for (int i = 0; i < 2; i++)
        #pragma unroll
        for (int j = 0; j < 8; j++)
            #pragma unroll
            for (int k = 0; k < 4; k++) acc[i][j][k] = 0.0f;

    const int KT = K / BK;

    // this thread's fixed load coordinates (same mapping as before)
    const int arow = tid >> 3, ac = tid & 7;   // used with +128-row offsets

    auto issue = [&](int kt, int buf) {        // prologue-only full issue
        int k0 = kt * BK;
        uint32_t ab = sbase + buf * STAGE;
        uint32_t bb = ab + ASTAGE;
        #pragma unroll
        for (int i = 0; i < 4; i++) {
            int row = arow + i * 32;
            cp16(ab + row * RSTR + ac * 16,
                 A + (size_t)(m0 + row) * lda + k0 + ac * 8);
        }
        #pragma unroll
        for (int i = 0; i < 4; i++) {
            int row = arow + i * 32;
            cp16(bb + row * RSTR + ac * 16,
                 Bt + (size_t)(n0 + row) * K + k0 + ac * 8);
        }
    };

    // one of this thread's 8 load chunks for tile nkt into buffer nbuf
    auto issue_chunk = [&](int ci, int nkt, int nbuf) {
        int k0 = nkt * BK;
        uint32_t tb = sbase + nbuf * STAGE;
        if (ci < 4) {
            int row = arow + ci * 32;
            cp16(tb + row * RSTR + ac * 16,
                 A + (size_t)(m0 + row) * lda + k0 + ac * 8);
        } else {
            int row = arow + (ci - 4) * 32;
            cp16(tb + ASTAGE + row * RSTR + ac * 16,
                 Bt + (size_t)(n0 + row) * K + k0 + ac * 8);
        }
    };

    // compute(kt) with issue of tile nkt interleaved (one chunk per 2 mma groups)
    auto body = [&](int buf, int nkt, int nbuf, bool di) {
        uint32_t ab = sbase + buf * STAGE;
        uint32_t bb = ab + ASTAGE;

        auto lda_ = [&](uint32_t* r, int ms, int ks) {
            int row = wm * 32 + ms * 16 + lr + ((lane >> 3) & 1) * 8;
            int ch  = ks * 2 + (lane >> 4);
            ldsm4(r, ab + row * RSTR + ch * 16);
        };
        auto ldb_ = [&](uint32_t* r, int np, int ks) {
            int row = wn * 64 + np * 16 + lr + (lane >> 4) * 8;
            int ch  = ks * 2 + ((lane >> 3) & 1);
            ldsm4(r, bb + row * RSTR + ch * 16);
        };

        uint32_t a[2][4], an[2][4];
        uint32_t bc[4], bn[4];

        lda_(a[0], 0, 0); lda_(a[1], 1, 0);
        ldb_(bc, 0, 0);

        #pragma unroll
        for (int ks = 0; ks < 4; ks++) {
            #pragma unroll
            for (int np = 0; np < 4; np++) {
                const int gi = ks * 4 + np;
                if ((gi & 1) == 0 && di) issue_chunk(gi >> 1, nkt, nbuf);

                if (np < 3)            ldb_(bn, np + 1, ks);
                else if (ks < 3)       ldb_(bn, 0, ks + 1);
                if (np == 0 && ks < 3) { lda_(an[0], 0, ks + 1); lda_(an[1], 1, ks + 1); }

                mma16(acc[0][2 * np],     a[0], bc[0], bc[1]);
                mma16(acc[0][2 * np + 1], a[0], bc[2], bc[3]);
                mma16(acc[1][2 * np],     a[1], bc[0], bc[1]);
                mma16(acc[1][2 * np + 1], a[1], bc[2], bc[3]);

                if (!(ks == 3 && np == 3)) {
                    bc[0] = bn[0]; bc[1] = bn[1]; bc[2] = bn[2]; bc[3] = bn[3];
                }
            }
            if (ks < 3) {
                #pragma unroll
                for (int q = 0; q < 4; q++) { a[0][q] = an[0][q]; a[1][q] = an[1][q]; }
            }
        }
    };

    issue(0, 0); CP_COMMIT();
    issue(1, 1); CP_COMMIT();

    // bias/W3 staged early (disjoint smem; loop syncs order it before epilogue)
    for (int i = tid; i < BN; i += 256) {
        sBias[i] = bias[n0 + i];
        if (EPI == 1) sW3[i] = W3[n0 + i];
    }

    for (int kt = 0; kt < KT; kt++) {
        int cur = kt - (kt / NSTG) * NSTG;            // kt % 3
        if (kt + 1 < KT) CP_WAIT1(); else CP_WAIT0();
        __syncthreads();
        bool di = (kt + 2 < KT);
        int nb = kt + 2;
        int nbuf = nb - (nb / NSTG) * NSTG;
        body(cur, nb, nbuf, di);
        if (di) CP_COMMIT();                          // commit ONLY when issued
    }

    if (EPI == 0) {
        __half* Cout = (__half*)CoutV;
        #pragma unroll
        for (int ms = 0; ms < 2; ms++) {
            int row = m0 + wm * 32 + ms * 16 + g;
            #pragma unroll
            for (int ns = 0; ns < 8; ns++) {
                int cl  = wn * 64 + ns * 8 + t * 2;
                int col = n0 + cl;
                __half2 v0 = __floats2half2_rn(
                    fmaxf(acc[ms][ns][0] + sBias[cl],     0.0f),
                    fmaxf(acc[ms][ns][1] + sBias[cl + 1], 0.0f));
                __half2 v1 = __floats2half2_rn(
                    fmaxf(acc[ms][ns][2] + sBias[cl],     0.0f),
                    fmaxf(acc[ms][ns][3] + sBias[cl + 1], 0.0f));
                *(__half2*)&Cout[(size_t)row * HID + col]       = v0;
                *(__half2*)&Cout[(size_t)(row + 8) * HID + col] = v1;
            }
        }
    } else {
        float* Cout = (float*)CoutV;
        float racc[2][2] = {{0.0f, 0.0f}, {0.0f, 0.0f}};
        #pragma unroll
        for (int ms = 0; ms < 2; ms++) {
            #pragma unroll
            for (int ns = 0; ns < 8; ns++) {
                int cl = wn * 64 + ns * 8 + t * 2;
                racc[ms][0] += fmaxf(acc[ms][ns][0] + sBias[cl],     0.0f) * sW3[cl]
                             + fmaxf(acc[ms][ns][1] + sBias[cl + 1], 0.0f) * sW3[cl + 1];
                racc[ms][1] += fmaxf(acc[ms][ns][2] + sBias[cl],     0.0f) * sW3[cl]
                             + fmaxf(acc[ms][ns][3] + sBias[cl + 1], 0.0f) * sW3[cl + 1];
            }
        }
        #pragma unroll
        for (int ms = 0; ms < 2; ms++) {
            #pragma unroll
            for (int rp = 0; rp < 2; rp++) {
                float p = racc[ms][rp];
                p += __shfl_xor_sync(0xffffffffu, p, 1);
                p += __shfl_xor_sync(0xffffffffu, p, 2);
                if (t == 0)
                    atomicAdd(&Cout[m0 + wm * 32 + ms * 16 + rp * 8 + g], p);
            }
        }
    }
}

// ---- launch: 4 kernels; gemm2 at index 3 (profiled) ----
extern "C" void kernel_launch(void* const* d_in, const int* in_sizes, int n_in,
                              void* d_out, int out_size) {
    const float* structures = (const float*)d_in[0];
    const float* E  = (const float*)d_in[1];
    const float* W1 = (const float*)d_in[2];
    const float* b1 = (const float*)d_in[3];
    const float* W2 = (const float*)d_in[4];
    const float* b2 = (const float*)d_in[5];
    const float* W3 = (const float*)d_in[6];
    const float* b3 = (const float*)d_in[7];
    float* out = (float*)d_out;

    __half *feat, *h1, *w1t, *w2t;
    cudaGetSymbolAddress((void**)&feat, g_feat);
    cudaGetSymbolAddress((void**)&h1,   g_h1);
    cudaGetSymbolAddress((void**)&w1t,  g_w1t);
    cudaGetSymbolAddress((void**)&w2t,  g_w2t);

    cudaFuncSetAttribute(gemm_kernel<0>, cudaFuncAttributeMaxDynamicSharedMemorySize, SMEM_BYTES);
    cudaFuncSetAttribute(gemm_kernel<1>, cudaFuncAttributeMaxDynamicSharedMemorySize, SMEM_BYTES);

    dim3 grid(HID / BN, BSZ / BM);   // (8, 1024)

    prep_all_kernel<<<1856, dim3(32, 8)>>>(W1, W2, b3, out, w1t, w2t);   // idx 0
    feat_kernel<<<BSZ / FROWS, FTHREADS>>>(structures, E, feat);         // idx 1
    gemm_kernel<0><<<grid, 256, SMEM_BYTES>>>(feat, KF, KF, w1t, b1,     // idx 2
                                              nullptr, (void*)h1);
    gemm_kernel<1><<<grid, 256, SMEM_BYTES>>>(h1, HID, HID, w2t, b2,     // idx 3 (profiled)
                                              W3, (void*)out);
}